// round 16
// baseline (speedup 1.0000x reference)
#include <cuda_runtime.h>
#include <cstdint>

// PositionEncoding: out[b,s,d] = x[b,s,d] + pe[s,d]
//   pe[s,d] = sin(s / 10000^(d/D)) if d even else cos(s / 10000^(d/D))
// Shapes: B=8, S=4096, D=1024 (fp32).
//
// R16: identical per-thread body to the best kernel (R6: 8 front-batched
// ldcg loads, trig overlapped, 8 add+stcg) but block=512 instead of 256.
// Same warps/SM (32) and same MLP, but half the CTAs per SM (oe 4 -> 2),
// which per the B300 spread model (spr = 1.10 + 25*(oe*MLP_p1 - 16)/T_CTA)
// drops oe*MLP_p1 from 32 to 16 = at threshold -> cross-CTA L1tex-queue
// contention spread falls to the 1.10 floor, trimming each wave's tail.

static constexpr int B = 8;
static constexpr int S = 4096;
static constexpr int D = 1024;
static constexpr int D4 = D / 4;                  // 256 float4 per row
static constexpr int SD4 = S * D4;                // 1,048,576
static constexpr int BSTR = S * D4;               // batch stride (float4)
static constexpr int THREADS = 512;

// log2(10000) / D  (D = 1024)
static constexpr float LOG2_10000_OVER_D = 13.287712379549449f / 1024.0f;

__global__ __launch_bounds__(THREADS)
void pe_add_kernel(const float4* __restrict__ x, float4* __restrict__ out) {
    int idx = blockIdx.x * THREADS + threadIdx.x;  // grid exactly covers SD4

    // ---- issue all 8 loads first (front-batched LDG.128, MLP=8) ----
    float4 v[B];
#pragma unroll
    for (int b = 0; b < B; b++) {
        v[b] = __ldcg(&x[idx + b * BSTR]);
    }

    // ---- compute PE while the loads are in flight ----
    int s  = idx >> 8;          // idx / D4
    int d4 = idx & (D4 - 1);    // idx % D4
    int d  = d4 << 2;
    float fs = (float)s;

    float a0 = fs * exp2f(-(float)(d + 0) * LOG2_10000_OVER_D);
    float a1 = fs * exp2f(-(float)(d + 1) * LOG2_10000_OVER_D);
    float a2 = fs * exp2f(-(float)(d + 2) * LOG2_10000_OVER_D);
    float a3 = fs * exp2f(-(float)(d + 3) * LOG2_10000_OVER_D);

    float pex = sinf(a0);   // even dim -> sin
    float pey = cosf(a1);   // odd dim  -> cos
    float pez = sinf(a2);
    float pew = cosf(a3);

    // ---- add + store all 8 ----
#pragma unroll
    for (int b = 0; b < B; b++) {
        float4 o;
        o.x = v[b].x + pex;
        o.y = v[b].y + pey;
        o.z = v[b].z + pez;
        o.w = v[b].w + pew;
        __stcg(&out[idx + b * BSTR], o);
    }
}

extern "C" void kernel_launch(void* const* d_in, const int* in_sizes, int n_in,
                              void* d_out, int out_size) {
    const float4* x = (const float4*)d_in[0];
    float4* out = (float4*)d_out;

    int blocks = SD4 / THREADS;   // 2048, exact
    pe_add_kernel<<<blocks, THREADS>>>(x, out);
}